// round 8
// baseline (speedup 1.0000x reference)
#include <cuda_runtime.h>
#include <cuda_bf16.h>
#include <math.h>
#include <stdint.h>

#define NNODE 50000
#define DDIM  256
#define HH    8
#define EE    500000
#define QKVW  768
#define ATT_SCALE 0.17677669529663687f  // 1/sqrt(32)

// ======================= device scratch ==========================================
__device__ float g_bcat[2][QKVW];
__device__ __nv_bfloat16 g_WcatT_hi[2][(size_t)QKVW * DDIM];  // [n][k], n = Q|K'|V'
__device__ __nv_bfloat16 g_WcatT_lo[2][(size_t)QKVW * DDIM];
__device__ __nv_bfloat16 g_WaT_hi[2][(size_t)DDIM * DDIM];
__device__ __nv_bfloat16 g_WaT_lo[2][(size_t)DDIM * DDIM];
__device__ __nv_bfloat16 g_fbf_hi[2][(size_t)NNODE * DDIM];
__device__ __nv_bfloat16 g_fbf_lo[2][(size_t)NNODE * DDIM];
__device__ __nv_bfloat16 g_hbf_hi[2][(size_t)NNODE * DDIM];
__device__ __nv_bfloat16 g_hbf_lo[2][(size_t)NNODE * DDIM];
__device__ float g_QKV[2][(size_t)NNODE * QKVW];  // fp32: Q(256)|K'(256)|V'(256)
__device__ float g_trans[2][(size_t)NNODE * DDIM];
// CSR-by-destination scratch
__device__ int g_deg[2][NNODE];
__device__ int g_rows[2][NNODE + 1];
__device__ int g_cursor[2][NNODE];
__device__ int g_esrc[2][EE];

// ======================= PTX helpers (base-target safe) ==========================
__device__ __forceinline__ uint32_t smem_u32(const void* p) {
    uint32_t a;
    asm("{ .reg .u64 t; cvta.to.shared.u64 t, %1; cvt.u32.u64 %0, t; }" : "=r"(a) : "l"(p));
    return a;
}
__device__ __forceinline__ void ldm_x4(uint32_t* r, uint32_t addr) {
    asm volatile("ldmatrix.sync.aligned.m8n8.x4.shared.b16 {%0,%1,%2,%3}, [%4];"
                 : "=r"(r[0]), "=r"(r[1]), "=r"(r[2]), "=r"(r[3]) : "r"(addr));
}
__device__ __forceinline__ void ldm_x2(uint32_t* r, uint32_t addr) {
    asm volatile("ldmatrix.sync.aligned.m8n8.x2.shared.b16 {%0,%1}, [%2];"
                 : "=r"(r[0]), "=r"(r[1]) : "r"(addr));
}
__device__ __forceinline__ void mma_bf16(float* c, const uint32_t* a, const uint32_t* b) {
    asm volatile("mma.sync.aligned.m16n8k16.row.col.f32.bf16.bf16.f32 "
                 "{%0,%1,%2,%3}, {%4,%5,%6,%7}, {%8,%9}, {%0,%1,%2,%3};"
                 : "+f"(c[0]), "+f"(c[1]), "+f"(c[2]), "+f"(c[3])
                 : "r"(a[0]), "r"(a[1]), "r"(a[2]), "r"(a[3]), "r"(b[0]), "r"(b[1]));
}
__device__ __forceinline__ void cp_async16(uint32_t dst, const void* src, int valid_bytes) {
    asm volatile("cp.async.cg.shared.global [%0], [%1], 16, %2;"
                 :: "r"(dst), "l"(src), "r"(valid_bytes));
}
#define CP_COMMIT() asm volatile("cp.async.commit_group;")
#define CP_WAIT(n)  asm volatile("cp.async.wait_group %0;" :: "n"(n))

// ======================= 1. prep: fold + transpose + bf16 split ==================
__global__ __launch_bounds__(256) void prep_kernel(
    const float* __restrict__ Wk, const float* __restrict__ bk,
    const float* __restrict__ Wq, const float* __restrict__ bq,
    const float* __restrict__ Wv, const float* __restrict__ bv,
    const float* __restrict__ Wa,
    const float* __restrict__ w_att, const float* __restrict__ w_msg)
{
    const int t = blockIdx.y;
    const int n = blockIdx.x;
    const int k = threadIdx.x;

    float val;
    if (n < 768) {
        if (n < 256) {
            val = Wq[((size_t)t * 256 + k) * 256 + n];
        } else {
            const int j = (n - 256) & 255;
            const int h = j >> 5, jj = j & 31;
            const float* W = (n < 512) ? Wk : Wv;
            const float* wm = ((n < 512) ? w_att : w_msg) + ((size_t)(t * 8 + h)) * 1024 + jj;
            const float* wrow = W + ((size_t)t * 256 + k) * 256 + h * 32;
            float a = 0.f;
            #pragma unroll 8
            for (int i = 0; i < 32; ++i) a += wrow[i] * wm[i * 32];
            val = a;
        }
        __nv_bfloat16 hi = __float2bfloat16(val);
        __nv_bfloat16 lo = __float2bfloat16(val - __bfloat162float(hi));
        g_WcatT_hi[t][(size_t)n * 256 + k] = hi;
        g_WcatT_lo[t][(size_t)n * 256 + k] = lo;
        if (k == 0) {
            float b;
            if (n < 256) b = bq[t * 256 + n];
            else {
                const int j = (n - 256) & 255;
                const int h = j >> 5, jj = j & 31;
                const float* bb = (n < 512) ? bk : bv;
                const float* wm = ((n < 512) ? w_att : w_msg) + ((size_t)(t * 8 + h)) * 1024 + jj;
                float a = 0.f;
                #pragma unroll 8
                for (int i = 0; i < 32; ++i) a += bb[t * 256 + h * 32 + i] * wm[i * 32];
                b = a;
            }
            g_bcat[t][n] = b;
        }
    } else {
        const int nn = n - 768;
        val = Wa[((size_t)t * 256 + k) * 256 + nn];
        __nv_bfloat16 hi = __float2bfloat16(val);
        __nv_bfloat16 lo = __float2bfloat16(val - __bfloat162float(hi));
        g_WaT_hi[t][(size_t)nn * 256 + k] = hi;
        g_WaT_lo[t][(size_t)nn * 256 + k] = lo;
    }
}

// ======================= 2. fp32 -> bf16 hi/lo split =============================
__global__ void convsplit_kernel(const float* __restrict__ src,
                                 __nv_bfloat16* __restrict__ hi,
                                 __nv_bfloat16* __restrict__ lo, long n4)
{
    long i = (long)blockIdx.x * blockDim.x + threadIdx.x;
    if (i >= n4) return;
    float4 v = ((const float4*)src)[i];
    __nv_bfloat16 h0 = __float2bfloat16(v.x), h1 = __float2bfloat16(v.y);
    __nv_bfloat16 h2 = __float2bfloat16(v.z), h3 = __float2bfloat16(v.w);
    __nv_bfloat16 l0 = __float2bfloat16(v.x - __bfloat162float(h0));
    __nv_bfloat16 l1 = __float2bfloat16(v.y - __bfloat162float(h1));
    __nv_bfloat16 l2 = __float2bfloat16(v.z - __bfloat162float(h2));
    __nv_bfloat16 l3 = __float2bfloat16(v.w - __bfloat162float(h3));
    ((__nv_bfloat162*)hi)[i * 2]     = __halves2bfloat162(h0, h1);
    ((__nv_bfloat162*)hi)[i * 2 + 1] = __halves2bfloat162(h2, h3);
    ((__nv_bfloat162*)lo)[i * 2]     = __halves2bfloat162(l0, l1);
    ((__nv_bfloat162*)lo)[i * 2 + 1] = __halves2bfloat162(l2, l3);
}

// ======================= 3. CSR build ============================================
__global__ void zerodeg_kernel()
{
    int i = blockIdx.x * blockDim.x + threadIdx.x;
    if (i < 2 * NNODE) ((int*)g_deg)[i] = 0;
}

__global__ void hist_kernel(const int* __restrict__ dst)
{
    const int et = blockIdx.y;
    int e = blockIdx.x * blockDim.x + threadIdx.x;
    if (e >= EE) return;
    atomicAdd(&g_deg[et][dst[(long)et * EE + e]], 1);
}

__global__ __launch_bounds__(1024) void scan_kernel()
{
    const int et = blockIdx.x;
    const int t = threadIdx.x;
    const int CH = (NNODE + 1023) / 1024;
    const int start = t * CH;

    int sum = 0;
    for (int i = 0; i < CH; ++i) {
        int idx = start + i;
        if (idx < NNODE) sum += g_deg[et][idx];
    }
    __shared__ int wsums[32];
    const int lane = t & 31, wid = t >> 5;
    int v = sum;
    #pragma unroll
    for (int o = 1; o < 32; o <<= 1) {
        int n = __shfl_up_sync(0xffffffffu, v, o);
        if (lane >= o) v += n;
    }
    if (lane == 31) wsums[wid] = v;
    __syncthreads();
    if (wid == 0) {
        int x = wsums[lane];
        #pragma unroll
        for (int o = 1; o < 32; o <<= 1) {
            int n = __shfl_up_sync(0xffffffffu, x, o);
            if (lane >= o) x += n;
        }
        wsums[lane] = x;
    }
    __syncthreads();
    int excl = v - sum + (wid > 0 ? wsums[wid - 1] : 0);

    int run = excl;
    for (int i = 0; i < CH; ++i) {
        int idx = start + i;
        if (idx < NNODE) {
            g_rows[et][idx] = run;
            g_cursor[et][idx] = run;
            run += g_deg[et][idx];
        }
    }
    if (t == 1023) g_rows[et][NNODE] = run;
}

__global__ void scatter_kernel(const int* __restrict__ src, const int* __restrict__ dst)
{
    const int et = blockIdx.y;
    int e = blockIdx.x * blockDim.x + threadIdx.x;
    if (e >= EE) return;
    int s = src[(long)et * EE + e];
    int d = dst[(long)et * EE + e];
    int pos = atomicAdd(&g_cursor[et][d], 1);
    g_esrc[et][pos] = s;
}

// ======================= 4. warp-per-dst aggregation (R4 2-edge unroll) ===========
__device__ __forceinline__ float dot8(const float4& qa, const float4& qb,
                                      const float4& ka, const float4& kb) {
    return qa.x * ka.x + qa.y * ka.y + qa.z * ka.z + qa.w * ka.w
         + qb.x * kb.x + qb.y * kb.y + qb.z * kb.z + qb.w * kb.w;
}

__global__ __launch_bounds__(256) void agg_kernel(const float* __restrict__ mu)
{
    const int et = blockIdx.y;
    const int dt = 1 - et;
    const int warp = threadIdx.x >> 5;
    const int lane = threadIdx.x & 31;
    const int node = blockIdx.x * 8 + warp;
    if (node >= NNODE) return;

    const int r0 = g_rows[et][node];
    const int r1 = g_rows[et][node + 1];

    const int h = lane >> 2;
    const int base = lane * 8;
    const float muh = mu[et * 8 + h] * ATT_SCALE;

    float acc[8];
    #pragma unroll
    for (int j = 0; j < 8; ++j) acc[j] = 0.f;
    float wsum = 0.f;

    if (r0 < r1) {
        const float* qrow = g_QKV[dt] + (size_t)node * QKVW + base;
        const float4 qa = *(const float4*)qrow;
        const float4 qb = *(const float4*)(qrow + 4);
        const int* __restrict__ ep = g_esrc[et];
        const float* __restrict__ kvbase = g_QKV[et];

        int j = r0;
        for (; j + 1 < r1; j += 2) {
            const int s0 = ep[j];
            const int s1 = ep[j + 1];
            const float* kr0 = kvbase + (size_t)s0 * QKVW + 256 + base;
            const float* kr1 = kvbase + (size_t)s1 * QKVW + 256 + base;
            float4 ka0 = *(const float4*)kr0;
            float4 kb0 = *(const float4*)(kr0 + 4);
            float4 va0 = *(const float4*)(kr0 + 256);
            float4 vb0 = *(const float4*)(kr0 + 260);
            float4 ka1 = *(const float4*)kr1;
            float4 kb1 = *(const float4*)(kr1 + 4);
            float4 va1 = *(const float4*)(kr1 + 256);
            float4 vb1 = *(const float4*)(kr1 + 260);

            float p0 = dot8(qa, qb, ka0, kb0);
            float p1 = dot8(qa, qb, ka1, kb1);
            p0 += __shfl_xor_sync(0xffffffffu, p0, 1);
            p1 += __shfl_xor_sync(0xffffffffu, p1, 1);
            p0 += __shfl_xor_sync(0xffffffffu, p0, 2);
            p1 += __shfl_xor_sync(0xffffffffu, p1, 2);

            float w0 = expf(p0 * muh);
            float w1 = expf(p1 * muh);
            wsum += w0 + w1;
            acc[0] += w0 * va0.x + w1 * va1.x;
            acc[1] += w0 * va0.y + w1 * va1.y;
            acc[2] += w0 * va0.z + w1 * va1.z;
            acc[3] += w0 * va0.w + w1 * va1.w;
            acc[4] += w0 * vb0.x + w1 * vb1.x;
            acc[5] += w0 * vb0.y + w1 * vb1.y;
            acc[6] += w0 * vb0.z + w1 * vb1.z;
            acc[7] += w0 * vb0.w + w1 * vb1.w;
        }
        if (j < r1) {
            const int s0 = ep[j];
            const float* kr0 = kvbase + (size_t)s0 * QKVW + 256 + base;
            float4 ka0 = *(const float4*)kr0;
            float4 kb0 = *(const float4*)(kr0 + 4);
            float4 va0 = *(const float4*)(kr0 + 256);
            float4 vb0 = *(const float4*)(kr0 + 260);
            float p0 = dot8(qa, qb, ka0, kb0);
            p0 += __shfl_xor_sync(0xffffffffu, p0, 1);
            p0 += __shfl_xor_sync(0xffffffffu, p0, 2);
            float w0 = expf(p0 * muh);
            wsum += w0;
            acc[0] += w0 * va0.x;  acc[1] += w0 * va0.y;
            acc[2] += w0 * va0.z;  acc[3] += w0 * va0.w;
            acc[4] += w0 * vb0.x;  acc[5] += w0 * vb0.y;
            acc[6] += w0 * vb0.z;  acc[7] += w0 * vb0.w;
        }
    }

    const float inv = (wsum > 0.f) ? 1.f / wsum : 0.f;
    __nv_bfloat162 hh[4], ll[4];
    #pragma unroll
    for (int j = 0; j < 4; ++j) {
        float x0 = acc[2 * j] * inv, x1 = acc[2 * j + 1] * inv;
        __nv_bfloat16 h0 = __float2bfloat16(x0), h1 = __float2bfloat16(x1);
        __nv_bfloat16 l0 = __float2bfloat16(x0 - __bfloat162float(h0));
        __nv_bfloat16 l1 = __float2bfloat16(x1 - __bfloat162float(h1));
        hh[j] = __halves2bfloat162(h0, h1);
        ll[j] = __halves2bfloat162(l0, l1);
    }
    const size_t o = (size_t)node * DDIM + base;
    *(uint4*)(g_hbf_hi[dt] + o) = *(const uint4*)hh;
    *(uint4*)(g_hbf_lo[dt] + o) = *(const uint4*)ll;
}

// ======================= 5. split-bf16 HMMA GEMM (4-stage cp.async pipeline) =====
// C[M, Ntot](fp32) = A[M,256] * B[Ntot,256]^T + bias, per type (blockIdx.z).
// NSTAGE=4 circular buffer, BK=32/stage, ONE __syncthreads per chunk, prefetch
// depth 3. 1 CTA/SM (160KB smem), 8 warps, warp tile 64x32.
#define BM 128
#define BN 128
#define BKP 32
#define PADS 40                          // bf16 elems per smem row (32 + 8 pad)
#define STG_A_HI 0
#define STG_A_LO (BM * PADS * 2)         // 10240
#define STG_B_HI (2 * BM * PADS * 2)     // 20480
#define STG_B_LO (3 * BM * PADS * 2)     // 30720
#define STAGE_BYTES (4 * BM * PADS * 2)  // 40960
#define NSTAGE 4
#define GEMM_SMEM (NSTAGE * STAGE_BYTES) // 163840
#define NCHUNK 8                         // 256 / BKP

__global__ __launch_bounds__(256, 1) void hmma_gemm_kernel(
    const __nv_bfloat16* __restrict__ Ahi, const __nv_bfloat16* __restrict__ Alo, long strideA,
    const __nv_bfloat16* __restrict__ Bhi, const __nv_bfloat16* __restrict__ Blo, long strideB,
    const float* __restrict__ bias, long strideBias,
    float* __restrict__ C, long strideC,
    int M, int Ntot)
{
    extern __shared__ char smem[];
    const uint32_t sbase = smem_u32(smem);

    const int tid = threadIdx.x;
    const int wid = tid >> 5, lane = tid & 31;
    const int t = blockIdx.z;
    const int m0 = blockIdx.x * BM;
    const int n0 = blockIdx.y * BN;
    const int mw = (wid & 1) * 64;
    const int nw = (wid >> 1) * 32;

    Ahi += (size_t)t * strideA;  Alo += (size_t)t * strideA;
    Bhi += (size_t)t * strideB;  Blo += (size_t)t * strideB;
    bias += (size_t)t * strideBias;
    C += (size_t)t * strideC;

    // per-thread load mapping: 2 row-chunks of 16B per tensor-half per stage
    const int lrow0 = tid >> 2,         lc0 = (tid & 3) * 8;
    const int lrow1 = (tid + 256) >> 2, lc1 = ((tid + 256) & 3) * 8;
    const int ga0 = (m0 + lrow0 < M) ? (m0 + lrow0) : 0;
    const int ga1 = (m0 + lrow1 < M) ? (m0 + lrow1) : 0;
    const int va0 = (m0 + lrow0 < M) ? 16 : 0;
    const int va1 = (m0 + lrow1 < M) ? 16 : 0;
    const uint32_t so0 = (uint32_t)(lrow0 * PADS + lc0) * 2;
    const uint32_t so1 = (uint32_t)(lrow1 * PADS + lc1) * 2;

    #define LOAD_STAGE(ks, buf) do { \
        const uint32_t sbuf = sbase + (buf) * STAGE_BYTES; \
        const int kofs = (ks) * BKP; \
        cp_async16(sbuf + STG_A_HI + so0, Ahi + (size_t)ga0 * 256 + kofs + lc0, va0); \
        cp_async16(sbuf + STG_A_LO + so0, Alo + (size_t)ga0 * 256 + kofs + lc0, va0); \
        cp_async16(sbuf + STG_A_HI + so1, Ahi + (size_t)ga1 * 256 + kofs + lc1, va1); \
        cp_async16(sbuf + STG_A_LO + so1, Alo + (size_t)ga1 * 256 + kofs + lc1, va1); \
        cp_async16(sbuf + STG_B_HI + so0, Bhi + (size_t)(n0 + lrow0) * 256 + kofs + lc0, 16); \
        cp_async16(sbuf + STG_B_LO + so0, Blo + (size_t)(n0 + lrow0) * 256 + kofs + lc0, 16); \
        cp_async16(sbuf + STG_B_HI + so1, Bhi + (size_t)(n0 + lrow1) * 256 + kofs + lc1, 16); \
        cp_async16(sbuf + STG_B_LO + so1, Blo + (size_t)(n0 + lrow1) * 256 + kofs + lc1, 16); \
        CP_COMMIT(); \
    } while (0)

    float acc[4][4][4];
    #pragma unroll
    for (int i = 0; i < 4; ++i)
        #pragma unroll
        for (int j = 0; j < 4; ++j)
            #pragma unroll
            for (int r = 0; r < 4; ++r) acc[i][j][r] = 0.f;

    // prologue: fill 3 stages
    LOAD_STAGE(0, 0);
    LOAD_STAGE(1, 1);
    LOAD_STAGE(2, 2);

    #pragma unroll 1
    for (int ks = 0; ks < NCHUNK; ++ks) {
        // wait until group ks is complete (committed = min(8, ks+3))
        if (ks <= NCHUNK - 3)      CP_WAIT(2);
        else if (ks == NCHUNK - 2) CP_WAIT(1);
        else                       CP_WAIT(0);
        __syncthreads();   // all warps done with buffer (ks-1)%4 AND stage ks visible

        if (ks + 3 < NCHUNK) LOAD_STAGE(ks + 3, (ks + 3) & 3);

        const uint32_t sbuf = sbase + (ks & 3) * STAGE_BYTES;
        #pragma unroll
        for (int kk = 0; kk < BKP / 16; ++kk) {
            uint32_t a_hi[4][4], a_lo[4][4], b_hi[4][2], b_lo[4][2];
            #pragma unroll
            for (int i = 0; i < 4; ++i) {
                uint32_t off = (uint32_t)((mw + i * 16 + (lane & 15)) * PADS
                                          + kk * 16 + (lane >> 4) * 8) * 2;
                ldm_x4(a_hi[i], sbuf + STG_A_HI + off);
                ldm_x4(a_lo[i], sbuf + STG_A_LO + off);
            }
            #pragma unroll
            for (int j = 0; j < 4; ++j) {
                uint32_t off = (uint32_t)((nw + j * 8 + (lane & 7)) * PADS
                                          + kk * 16 + ((lane >> 3) & 1) * 8) * 2;
                ldm_x2(b_hi[j], sbuf + STG_B_HI + off);
                ldm_x2(b_lo[j], sbuf + STG_B_LO + off);
            }
            #pragma unroll
            for (int i = 0; i < 4; ++i)
                #pragma unroll
                for (int j = 0; j < 4; ++j) {
                    mma_bf16(acc[i][j], a_hi[i], b_hi[j]);
                    mma_bf16(acc[i][j], a_hi[i], b_lo[j]);
                    mma_bf16(acc[i][j], a_lo[i], b_hi[j]);
                }
        }
    }

    #pragma unroll
    for (int i = 0; i < 4; ++i) {
        int r0 = m0 + mw + i * 16 + (lane >> 2);
        int r1 = r0 + 8;
        #pragma unroll
        for (int j = 0; j < 4; ++j) {
            int col = n0 + nw + j * 8 + (lane & 3) * 2;
            float b0 = bias[col], b1 = bias[col + 1];
            if (r0 < M) {
                float2 o = make_float2(acc[i][j][0] + b0, acc[i][j][1] + b1);
                *(float2*)(C + (size_t)r0 * Ntot + col) = o;
            }
            if (r1 < M) {
                float2 o = make_float2(acc[i][j][2] + b0, acc[i][j][3] + b1);
                *(float2*)(C + (size_t)r1 * Ntot + col) = o;
            }
        }
    }
}

// ======================= 6. skip-mix + LayerNorm =================================
__global__ __launch_bounds__(256) void ln_kernel(
    const float* __restrict__ feats, const float* __restrict__ skip,
    const float* __restrict__ ln_w, const float* __restrict__ ln_b,
    float* __restrict__ out)
{
    long row = (long)blockIdx.x * 8 + (threadIdx.x >> 5);
    const int lane = threadIdx.x & 31;
    const int t = (int)(row / NNODE);
    const float alpha = 1.f / (1.f + expf(-skip[t]));
    const float beta = 1.f - alpha;

    const float* tr = (const float*)g_trans + row * DDIM + lane * 8;
    const float* ft = feats + row * DDIM + lane * 8;

    float v[8];
    float4 t0 = *(const float4*)(tr);
    float4 t1 = *(const float4*)(tr + 4);
    float4 f0 = *(const float4*)(ft);
    float4 f1 = *(const float4*)(ft + 4);
    v[0] = alpha * t0.x + beta * f0.x;  v[1] = alpha * t0.y + beta * f0.y;
    v[2] = alpha * t0.z + beta * f0.z;  v[3] = alpha * t0.w + beta * f0.w;
    v[4] = alpha * t1.x + beta * f1.x;  v[5] = alpha * t1.y + beta * f1.y;
    v[6] = alpha * t1.z + beta * f1.z;  v[7] = alpha * t1.w + beta * f1.w;

    float sum = 0.f, sq = 0.f;
    #pragma unroll
    for (int j = 0; j < 8; ++j) { sum += v[j]; sq += v[j] * v[j]; }
    #pragma unroll
    for (int o = 16; o > 0; o >>= 1) {
        sum += __shfl_xor_sync(0xffffffffu, sum, o);
        sq  += __shfl_xor_sync(0xffffffffu, sq, o);
    }
    const float mean = sum * (1.f / 256.f);
    const float var  = sq * (1.f / 256.f) - mean * mean;
    const float rstd = rsqrtf(var + 1e-5f);

    const int cbase = t * 256 + lane * 8;
    float* op = out + row * DDIM + lane * 8;
    float4 o0, o1;
    o0.x = (v[0] - mean) * rstd * ln_w[cbase + 0] + ln_b[cbase + 0];
    o0.y = (v[1] - mean) * rstd * ln_w[cbase + 1] + ln_b[cbase + 1];
    o0.z = (v[2] - mean) * rstd * ln_w[cbase + 2] + ln_b[cbase + 2];
    o0.w = (v[3] - mean) * rstd * ln_w[cbase + 3] + ln_b[cbase + 3];
    o1.x = (v[4] - mean) * rstd * ln_w[cbase + 4] + ln_b[cbase + 4];
    o1.y = (v[5] - mean) * rstd * ln_w[cbase + 5] + ln_b[cbase + 5];
    o1.z = (v[6] - mean) * rstd * ln_w[cbase + 6] + ln_b[cbase + 6];
    o1.w = (v[7] - mean) * rstd * ln_w[cbase + 7] + ln_b[cbase + 7];
    *(float4*)(op)     = o0;
    *(float4*)(op + 4) = o1;
}

// ======================= host launch =============================================
extern "C" void kernel_launch(void* const* d_in, const int* in_sizes, int n_in,
                              void* d_out, int out_size)
{
    const float* feats = (const float*)d_in[0];
    const float* Wk    = (const float*)d_in[1];
    const float* bk    = (const float*)d_in[2];
    const float* Wq    = (const float*)d_in[3];
    const float* bq    = (const float*)d_in[4];
    const float* Wv    = (const float*)d_in[5];
    const float* bv    = (const float*)d_in[6];
    const float* Wa    = (const float*)d_in[7];
    const float* ba    = (const float*)d_in[8];
    const float* ln_w  = (const float*)d_in[9];
    const float* ln_b  = (const float*)d_in[10];
    const float* skip  = (const float*)d_in[11];
    const float* mu    = (const float*)d_in[12];
    const float* w_att = (const float*)d_in[13];
    const float* w_msg = (const float*)d_in[14];
    const int*   src   = (const int*)d_in[15];
    const int*   dst   = (const int*)d_in[16];
    float* out = (float*)d_out;

    static bool attr_done = false;
    if (!attr_done) {
        cudaFuncSetAttribute(hmma_gemm_kernel,
                             cudaFuncAttributeMaxDynamicSharedMemorySize, GEMM_SMEM);
        attr_done = true;
    }

    float *pbcat, *pQKV, *ptrans;
    __nv_bfloat16 *pWcH, *pWcL, *pWaH, *pWaL, *pfH, *pfL, *phH, *phL;
    cudaGetSymbolAddress((void**)&pbcat, g_bcat);
    cudaGetSymbolAddress((void**)&pQKV, g_QKV);
    cudaGetSymbolAddress((void**)&ptrans, g_trans);
    cudaGetSymbolAddress((void**)&pWcH, g_WcatT_hi);
    cudaGetSymbolAddress((void**)&pWcL, g_WcatT_lo);
    cudaGetSymbolAddress((void**)&pWaH, g_WaT_hi);
    cudaGetSymbolAddress((void**)&pWaL, g_WaT_lo);
    cudaGetSymbolAddress((void**)&pfH, g_fbf_hi);
    cudaGetSymbolAddress((void**)&pfL, g_fbf_lo);
    cudaGetSymbolAddress((void**)&phH, g_hbf_hi);
    cudaGetSymbolAddress((void**)&phL, g_hbf_lo);

    // 1. weight prep
    {
        dim3 grid(1024, 2);
        prep_kernel<<<grid, 256>>>(Wk, bk, Wq, bq, Wv, bv, Wa, w_att, w_msg);
    }

    // 2. feats -> bf16 hi/lo
    {
        const long n4 = 2L * NNODE * DDIM / 4;
        convsplit_kernel<<<(int)((n4 + 255) / 256), 256>>>(feats, pfH, pfL, n4);
    }

    // 3. CSR build
    zerodeg_kernel<<<(2 * NNODE + 255) / 256, 256>>>();
    {
        dim3 grid((EE + 255) / 256, 2);
        hist_kernel<<<grid, 256>>>(dst);
    }
    scan_kernel<<<2, 1024>>>();
    {
        dim3 grid((EE + 255) / 256, 2);
        scatter_kernel<<<grid, 256>>>(src, dst);
    }

    // 4. QKV projection (pipelined HMMA)
    {
        dim3 grid((NNODE + BM - 1) / BM, QKVW / BN, 2);
        hmma_gemm_kernel<<<grid, 256, GEMM_SMEM>>>(
            pfH, pfL, (long)NNODE * DDIM,
            pWcH, pWcL, (long)QKVW * DDIM,
            pbcat, (long)QKVW,
            pQKV, (long)NNODE * QKVW,
            NNODE, QKVW);
    }

    // 5. aggregation
    {
        dim3 grid((NNODE + 7) / 8, 2);
        agg_kernel<<<grid, 256>>>(mu);
    }

    // 6. output projection (pipelined HMMA)
    {
        dim3 grid((NNODE + BM - 1) / BM, DDIM / BN, 2);
        hmma_gemm_kernel<<<grid, 256, GEMM_SMEM>>>(
            phH, phL, (long)NNODE * DDIM,
            pWaH, pWaL, (long)DDIM * DDIM,
            ba, (long)DDIM,
            ptrans, (long)NNODE * DDIM,
            NNODE, DDIM);
    }

    // 7. skip-mix + LayerNorm -> d_out
    ln_kernel<<<(2 * NNODE) / 8, 256>>>(feats, skip, ln_w, ln_b, out);
}

// round 9
// speedup vs baseline: 1.0884x; 1.0884x over previous
#include <cuda_runtime.h>
#include <cuda_bf16.h>
#include <math.h>
#include <stdint.h>

#define NNODE 50000
#define DDIM  256
#define HH    8
#define EE    500000
#define QKVW  768
#define ATT_SCALE 0.17677669529663687f  // 1/sqrt(32)

// ======================= device scratch ==========================================
__device__ float g_bcat[2][QKVW];
__device__ __nv_bfloat16 g_WcatT_hi[2][(size_t)QKVW * DDIM];  // [n][k], n = Q|K'|V'
__device__ __nv_bfloat16 g_WcatT_lo[2][(size_t)QKVW * DDIM];
__device__ __nv_bfloat16 g_WaT_hi[2][(size_t)DDIM * DDIM];
__device__ __nv_bfloat16 g_WaT_lo[2][(size_t)DDIM * DDIM];
__device__ float g_QKV[2][(size_t)NNODE * QKVW];  // fp32: Q(256)|K'(256)|V'(256)
__device__ float g_h[2][(size_t)NNODE * DDIM];    // fp32 aggregated messages
__device__ float g_trans[2][(size_t)NNODE * DDIM];
// CSR-by-destination scratch
__device__ int g_deg[2][NNODE];
__device__ int g_rows[2][NNODE + 1];
__device__ int g_cursor[2][NNODE];
__device__ int g_esrc[2][EE];

// ======================= PTX helpers (base-target safe) ==========================
__device__ __forceinline__ uint32_t smem_u32(const void* p) {
    uint32_t a;
    asm("{ .reg .u64 t; cvta.to.shared.u64 t, %1; cvt.u32.u64 %0, t; }" : "=r"(a) : "l"(p));
    return a;
}
__device__ __forceinline__ void ldm_x4(uint32_t* r, uint32_t addr) {
    asm volatile("ldmatrix.sync.aligned.m8n8.x4.shared.b16 {%0,%1,%2,%3}, [%4];"
                 : "=r"(r[0]), "=r"(r[1]), "=r"(r[2]), "=r"(r[3]) : "r"(addr));
}
__device__ __forceinline__ void ldm_x2(uint32_t* r, uint32_t addr) {
    asm volatile("ldmatrix.sync.aligned.m8n8.x2.shared.b16 {%0,%1}, [%2];"
                 : "=r"(r[0]), "=r"(r[1]) : "r"(addr));
}
__device__ __forceinline__ void mma_bf16(float* c, const uint32_t* a, const uint32_t* b) {
    asm volatile("mma.sync.aligned.m16n8k16.row.col.f32.bf16.bf16.f32 "
                 "{%0,%1,%2,%3}, {%4,%5,%6,%7}, {%8,%9}, {%0,%1,%2,%3};"
                 : "+f"(c[0]), "+f"(c[1]), "+f"(c[2]), "+f"(c[3])
                 : "r"(a[0]), "r"(a[1]), "r"(a[2]), "r"(a[3]), "r"(b[0]), "r"(b[1]));
}

// split 8 fp32 into bf16 hi/lo packed uint4s
__device__ __forceinline__ void split8(const float4& v0, const float4& v1,
                                       uint4& hiq, uint4& loq) {
    float f[8] = {v0.x, v0.y, v0.z, v0.w, v1.x, v1.y, v1.z, v1.w};
    __nv_bfloat162 hh[4], ll[4];
    #pragma unroll
    for (int j = 0; j < 4; ++j) {
        __nv_bfloat16 h0 = __float2bfloat16(f[2 * j]);
        __nv_bfloat16 h1 = __float2bfloat16(f[2 * j + 1]);
        __nv_bfloat16 l0 = __float2bfloat16(f[2 * j]     - __bfloat162float(h0));
        __nv_bfloat16 l1 = __float2bfloat16(f[2 * j + 1] - __bfloat162float(h1));
        hh[j] = __halves2bfloat162(h0, h1);
        ll[j] = __halves2bfloat162(l0, l1);
    }
    hiq = *(const uint4*)hh;
    loq = *(const uint4*)ll;
}

// ======================= 1. prep: fold + transpose + bf16 split ==================
__global__ __launch_bounds__(256) void prep_kernel(
    const float* __restrict__ Wk, const float* __restrict__ bk,
    const float* __restrict__ Wq, const float* __restrict__ bq,
    const float* __restrict__ Wv, const float* __restrict__ bv,
    const float* __restrict__ Wa,
    const float* __restrict__ w_att, const float* __restrict__ w_msg)
{
    const int t = blockIdx.y;
    const int n = blockIdx.x;
    const int k = threadIdx.x;

    float val;
    if (n < 768) {
        if (n < 256) {
            val = Wq[((size_t)t * 256 + k) * 256 + n];
        } else {
            const int j = (n - 256) & 255;
            const int h = j >> 5, jj = j & 31;
            const float* W = (n < 512) ? Wk : Wv;
            const float* wm = ((n < 512) ? w_att : w_msg) + ((size_t)(t * 8 + h)) * 1024 + jj;
            const float* wrow = W + ((size_t)t * 256 + k) * 256 + h * 32;
            float a = 0.f;
            #pragma unroll 8
            for (int i = 0; i < 32; ++i) a += wrow[i] * wm[i * 32];
            val = a;
        }
        __nv_bfloat16 hi = __float2bfloat16(val);
        __nv_bfloat16 lo = __float2bfloat16(val - __bfloat162float(hi));
        g_WcatT_hi[t][(size_t)n * 256 + k] = hi;
        g_WcatT_lo[t][(size_t)n * 256 + k] = lo;
        if (k == 0) {
            float b;
            if (n < 256) b = bq[t * 256 + n];
            else {
                const int j = (n - 256) & 255;
                const int h = j >> 5, jj = j & 31;
                const float* bb = (n < 512) ? bk : bv;
                const float* wm = ((n < 512) ? w_att : w_msg) + ((size_t)(t * 8 + h)) * 1024 + jj;
                float a = 0.f;
                #pragma unroll 8
                for (int i = 0; i < 32; ++i) a += bb[t * 256 + h * 32 + i] * wm[i * 32];
                b = a;
            }
            g_bcat[t][n] = b;
        }
    } else {
        const int nn = n - 768;
        val = Wa[((size_t)t * 256 + k) * 256 + nn];
        __nv_bfloat16 hi = __float2bfloat16(val);
        __nv_bfloat16 lo = __float2bfloat16(val - __bfloat162float(hi));
        g_WaT_hi[t][(size_t)nn * 256 + k] = hi;
        g_WaT_lo[t][(size_t)nn * 256 + k] = lo;
    }
}

// ======================= 2. CSR build ============================================
__global__ void zerodeg_kernel()
{
    int i = blockIdx.x * blockDim.x + threadIdx.x;
    if (i < 2 * NNODE) ((int*)g_deg)[i] = 0;
}

__global__ void hist_kernel(const int* __restrict__ dst)
{
    const int et = blockIdx.y;
    int e = blockIdx.x * blockDim.x + threadIdx.x;
    if (e >= EE) return;
    atomicAdd(&g_deg[et][dst[(long)et * EE + e]], 1);
}

__global__ __launch_bounds__(1024) void scan_kernel()
{
    const int et = blockIdx.x;
    const int t = threadIdx.x;
    const int CH = (NNODE + 1023) / 1024;
    const int start = t * CH;

    int sum = 0;
    for (int i = 0; i < CH; ++i) {
        int idx = start + i;
        if (idx < NNODE) sum += g_deg[et][idx];
    }
    __shared__ int wsums[32];
    const int lane = t & 31, wid = t >> 5;
    int v = sum;
    #pragma unroll
    for (int o = 1; o < 32; o <<= 1) {
        int n = __shfl_up_sync(0xffffffffu, v, o);
        if (lane >= o) v += n;
    }
    if (lane == 31) wsums[wid] = v;
    __syncthreads();
    if (wid == 0) {
        int x = wsums[lane];
        #pragma unroll
        for (int o = 1; o < 32; o <<= 1) {
            int n = __shfl_up_sync(0xffffffffu, x, o);
            if (lane >= o) x += n;
        }
        wsums[lane] = x;
    }
    __syncthreads();
    int excl = v - sum + (wid > 0 ? wsums[wid - 1] : 0);

    int run = excl;
    for (int i = 0; i < CH; ++i) {
        int idx = start + i;
        if (idx < NNODE) {
            g_rows[et][idx] = run;
            g_cursor[et][idx] = run;
            run += g_deg[et][idx];
        }
    }
    if (t == 1023) g_rows[et][NNODE] = run;
}

__global__ void scatter_kernel(const int* __restrict__ src, const int* __restrict__ dst)
{
    const int et = blockIdx.y;
    int e = blockIdx.x * blockDim.x + threadIdx.x;
    if (e >= EE) return;
    int s = src[(long)et * EE + e];
    int d = dst[(long)et * EE + e];
    int pos = atomicAdd(&g_cursor[et][d], 1);
    g_esrc[et][pos] = s;
}

// ======================= 3. warp-per-dst aggregation (2-edge unroll) ==============
__device__ __forceinline__ float dot8(const float4& qa, const float4& qb,
                                      const float4& ka, const float4& kb) {
    return qa.x * ka.x + qa.y * ka.y + qa.z * ka.z + qa.w * ka.w
         + qb.x * kb.x + qb.y * kb.y + qb.z * kb.z + qb.w * kb.w;
}

__global__ __launch_bounds__(256) void agg_kernel(const float* __restrict__ mu)
{
    const int et = blockIdx.y;
    const int dt = 1 - et;
    const int warp = threadIdx.x >> 5;
    const int lane = threadIdx.x & 31;
    const int node = blockIdx.x * 8 + warp;
    if (node >= NNODE) return;

    const int r0 = g_rows[et][node];
    const int r1 = g_rows[et][node + 1];

    const int h = lane >> 2;
    const int base = lane * 8;
    const float muh = mu[et * 8 + h] * ATT_SCALE;

    float acc[8];
    #pragma unroll
    for (int j = 0; j < 8; ++j) acc[j] = 0.f;
    float wsum = 0.f;

    if (r0 < r1) {
        const float* qrow = g_QKV[dt] + (size_t)node * QKVW + base;
        const float4 qa = *(const float4*)qrow;
        const float4 qb = *(const float4*)(qrow + 4);
        const int* __restrict__ ep = g_esrc[et];
        const float* __restrict__ kvbase = g_QKV[et];

        int j = r0;
        for (; j + 1 < r1; j += 2) {
            const int s0 = ep[j];
            const int s1 = ep[j + 1];
            const float* kr0 = kvbase + (size_t)s0 * QKVW + 256 + base;
            const float* kr1 = kvbase + (size_t)s1 * QKVW + 256 + base;
            float4 ka0 = *(const float4*)kr0;
            float4 kb0 = *(const float4*)(kr0 + 4);
            float4 va0 = *(const float4*)(kr0 + 256);
            float4 vb0 = *(const float4*)(kr0 + 260);
            float4 ka1 = *(const float4*)kr1;
            float4 kb1 = *(const float4*)(kr1 + 4);
            float4 va1 = *(const float4*)(kr1 + 256);
            float4 vb1 = *(const float4*)(kr1 + 260);

            float p0 = dot8(qa, qb, ka0, kb0);
            float p1 = dot8(qa, qb, ka1, kb1);
            p0 += __shfl_xor_sync(0xffffffffu, p0, 1);
            p1 += __shfl_xor_sync(0xffffffffu, p1, 1);
            p0 += __shfl_xor_sync(0xffffffffu, p0, 2);
            p1 += __shfl_xor_sync(0xffffffffu, p1, 2);

            float w0 = expf(p0 * muh);
            float w1 = expf(p1 * muh);
            wsum += w0 + w1;
            acc[0] += w0 * va0.x + w1 * va1.x;
            acc[1] += w0 * va0.y + w1 * va1.y;
            acc[2] += w0 * va0.z + w1 * va1.z;
            acc[3] += w0 * va0.w + w1 * va1.w;
            acc[4] += w0 * vb0.x + w1 * vb1.x;
            acc[5] += w0 * vb0.y + w1 * vb1.y;
            acc[6] += w0 * vb0.z + w1 * vb1.z;
            acc[7] += w0 * vb0.w + w1 * vb1.w;
        }
        if (j < r1) {
            const int s0 = ep[j];
            const float* kr0 = kvbase + (size_t)s0 * QKVW + 256 + base;
            float4 ka0 = *(const float4*)kr0;
            float4 kb0 = *(const float4*)(kr0 + 4);
            float4 va0 = *(const float4*)(kr0 + 256);
            float4 vb0 = *(const float4*)(kr0 + 260);
            float p0 = dot8(qa, qb, ka0, kb0);
            p0 += __shfl_xor_sync(0xffffffffu, p0, 1);
            p0 += __shfl_xor_sync(0xffffffffu, p0, 2);
            float w0 = expf(p0 * muh);
            wsum += w0;
            acc[0] += w0 * va0.x;  acc[1] += w0 * va0.y;
            acc[2] += w0 * va0.z;  acc[3] += w0 * va0.w;
            acc[4] += w0 * vb0.x;  acc[5] += w0 * vb0.y;
            acc[6] += w0 * vb0.z;  acc[7] += w0 * vb0.w;
        }
    }

    const float inv = (wsum > 0.f) ? 1.f / wsum : 0.f;
    float* op = g_h[dt] + (size_t)node * DDIM + base;
    float4 o0 = make_float4(acc[0] * inv, acc[1] * inv, acc[2] * inv, acc[3] * inv);
    float4 o1 = make_float4(acc[4] * inv, acc[5] * inv, acc[6] * inv, acc[7] * inv);
    *(float4*)(op)     = o0;
    *(float4*)(op + 4) = o1;
}

// ======================= 4. split-bf16 HMMA GEMM (fp32 A, in-kernel split) =======
// C[M, Ntot](fp32) = A[M,256](fp32) * B[Ntot,256]^T(bf16 hi/lo) + bias, per type.
// A is converted to bf16 hi/lo in registers during smem staging.
// Block: 256 thr (8 warps), tile 128x128, BK=64. Warp tile 64x32. (R4 structure.)
#define BM 128
#define BN 128
#define BK 64
#define LDS_STRIDE 72
#define AS_HI 0
#define AS_LO (AS_HI + BM * LDS_STRIDE * 2)
#define BS_HI (AS_LO + BM * LDS_STRIDE * 2)
#define BS_LO (BS_HI + BN * LDS_STRIDE * 2)
#define GEMM_SMEM (BS_LO + BN * LDS_STRIDE * 2)

__global__ __launch_bounds__(256) void hmma_gemm_kernel(
    const float* __restrict__ A, long strideA,
    const __nv_bfloat16* __restrict__ Bhi, const __nv_bfloat16* __restrict__ Blo, long strideB,
    const float* __restrict__ bias, long strideBias,
    float* __restrict__ C, long strideC,
    int M, int Ntot)
{
    extern __shared__ char smem[];
    const uint32_t sbase = smem_u32(smem);

    const int tid = threadIdx.x;
    const int wid = tid >> 5, lane = tid & 31;
    const int t = blockIdx.z;
    const int m0 = blockIdx.x * BM;
    const int n0 = blockIdx.y * BN;
    const int mw = (wid & 1) * 64;
    const int nw = (wid >> 1) * 32;

    A += (size_t)t * strideA;
    Bhi += (size_t)t * strideB;  Blo += (size_t)t * strideB;
    bias += (size_t)t * strideBias;
    C += (size_t)t * strideC;

    float acc[4][4][4];
    #pragma unroll
    for (int i = 0; i < 4; ++i)
        #pragma unroll
        for (int j = 0; j < 4; ++j)
            #pragma unroll
            for (int r = 0; r < 4; ++r) acc[i][j][r] = 0.f;

    for (int kofs = 0; kofs < 256; kofs += BK) {
        __syncthreads();
        // ---- load A tile (128 x 64 fp32), split to hi/lo bf16 in registers ----
        #pragma unroll
        for (int i = 0; i < 4; ++i) {
            int idx = tid + i * 256;
            int row = idx >> 3, c = (idx & 7) * 8;
            uint32_t soff = (uint32_t)(row * LDS_STRIDE + c) * 2;
            float4 v0 = make_float4(0.f, 0.f, 0.f, 0.f);
            float4 v1 = make_float4(0.f, 0.f, 0.f, 0.f);
            int gr = m0 + row;
            if (gr < M) {
                const float* ap = A + (size_t)gr * 256 + kofs + c;
                v0 = *(const float4*)ap;
                v1 = *(const float4*)(ap + 4);
            }
            uint4 hiq, loq;
            split8(v0, v1, hiq, loq);
            *(uint4*)(smem + AS_HI + soff) = hiq;
            *(uint4*)(smem + AS_LO + soff) = loq;
        }
        // ---- load B tile (128 x 64 hi & lo bf16) ----
        #pragma unroll
        for (int i = 0; i < 4; ++i) {
            int idx = tid + i * 256;
            int row = idx >> 3, c = (idx & 7) * 8;
            uint32_t soff = (uint32_t)(row * LDS_STRIDE + c) * 2;
            size_t s = (size_t)(n0 + row) * 256 + kofs + c;
            *(uint4*)(smem + BS_HI + soff) = *(const uint4*)(Bhi + s);
            *(uint4*)(smem + BS_LO + soff) = *(const uint4*)(Blo + s);
        }
        __syncthreads();

        #pragma unroll
        for (int kk = 0; kk < BK / 16; ++kk) {
            uint32_t a_hi[4][4], a_lo[4][4], b_hi[4][2], b_lo[4][2];
            #pragma unroll
            for (int i = 0; i < 4; ++i) {
                uint32_t off = (uint32_t)((mw + i * 16 + (lane & 15)) * LDS_STRIDE
                                          + kk * 16 + (lane >> 4) * 8) * 2;
                ldm_x4(a_hi[i], sbase + AS_HI + off);
                ldm_x4(a_lo[i], sbase + AS_LO + off);
            }
            #pragma unroll
            for (int j = 0; j < 4; ++j) {
                uint32_t off = (uint32_t)((nw + j * 8 + (lane & 7)) * LDS_STRIDE
                                          + kk * 16 + ((lane >> 3) & 1) * 8) * 2;
                ldm_x2(b_hi[j], sbase + BS_HI + off);
                ldm_x2(b_lo[j], sbase + BS_LO + off);
            }
            #pragma unroll
            for (int i = 0; i < 4; ++i)
                #pragma unroll
                for (int j = 0; j < 4; ++j) {
                    mma_bf16(acc[i][j], a_hi[i], b_hi[j]);
                    mma_bf16(acc[i][j], a_hi[i], b_lo[j]);
                    mma_bf16(acc[i][j], a_lo[i], b_hi[j]);
                }
        }
    }

    #pragma unroll
    for (int i = 0; i < 4; ++i) {
        int r0 = m0 + mw + i * 16 + (lane >> 2);
        int r1 = r0 + 8;
        #pragma unroll
        for (int j = 0; j < 4; ++j) {
            int col = n0 + nw + j * 8 + (lane & 3) * 2;
            float b0 = bias[col], b1 = bias[col + 1];
            if (r0 < M) {
                float2 o = make_float2(acc[i][j][0] + b0, acc[i][j][1] + b1);
                *(float2*)(C + (size_t)r0 * Ntot + col) = o;
            }
            if (r1 < M) {
                float2 o = make_float2(acc[i][j][2] + b0, acc[i][j][3] + b1);
                *(float2*)(C + (size_t)r1 * Ntot + col) = o;
            }
        }
    }
}

// ======================= 5. skip-mix + LayerNorm =================================
__global__ __launch_bounds__(256) void ln_kernel(
    const float* __restrict__ feats, const float* __restrict__ skip,
    const float* __restrict__ ln_w, const float* __restrict__ ln_b,
    float* __restrict__ out)
{
    long row = (long)blockIdx.x * 8 + (threadIdx.x >> 5);
    const int lane = threadIdx.x & 31;
    const int t = (int)(row / NNODE);
    const float alpha = 1.f / (1.f + expf(-skip[t]));
    const float beta = 1.f - alpha;

    const float* tr = (const float*)g_trans + row * DDIM + lane * 8;
    const float* ft = feats + row * DDIM + lane * 8;

    float v[8];
    float4 t0 = *(const float4*)(tr);
    float4 t1 = *(const float4*)(tr + 4);
    float4 f0 = *(const float4*)(ft);
    float4 f1 = *(const float4*)(ft + 4);
    v[0] = alpha * t0.x + beta * f0.x;  v[1] = alpha * t0.y + beta * f0.y;
    v[2] = alpha * t0.z + beta * f0.z;  v[3] = alpha * t0.w + beta * f0.w;
    v[4] = alpha * t1.x + beta * f1.x;  v[5] = alpha * t1.y + beta * f1.y;
    v[6] = alpha * t1.z + beta * f1.z;  v[7] = alpha * t1.w + beta * f1.w;

    float sum = 0.f, sq = 0.f;
    #pragma unroll
    for (int j = 0; j < 8; ++j) { sum += v[j]; sq += v[j] * v[j]; }
    #pragma unroll
    for (int o = 16; o > 0; o >>= 1) {
        sum += __shfl_xor_sync(0xffffffffu, sum, o);
        sq  += __shfl_xor_sync(0xffffffffu, sq, o);
    }
    const float mean = sum * (1.f / 256.f);
    const float var  = sq * (1.f / 256.f) - mean * mean;
    const float rstd = rsqrtf(var + 1e-5f);

    const int cbase = t * 256 + lane * 8;
    float* op = out + row * DDIM + lane * 8;
    float4 o0, o1;
    o0.x = (v[0] - mean) * rstd * ln_w[cbase + 0] + ln_b[cbase + 0];
    o0.y = (v[1] - mean) * rstd * ln_w[cbase + 1] + ln_b[cbase + 1];
    o0.z = (v[2] - mean) * rstd * ln_w[cbase + 2] + ln_b[cbase + 2];
    o0.w = (v[3] - mean) * rstd * ln_w[cbase + 3] + ln_b[cbase + 3];
    o1.x = (v[4] - mean) * rstd * ln_w[cbase + 4] + ln_b[cbase + 4];
    o1.y = (v[5] - mean) * rstd * ln_w[cbase + 5] + ln_b[cbase + 5];
    o1.z = (v[6] - mean) * rstd * ln_w[cbase + 6] + ln_b[cbase + 6];
    o1.w = (v[7] - mean) * rstd * ln_w[cbase + 7] + ln_b[cbase + 7];
    *(float4*)(op)     = o0;
    *(float4*)(op + 4) = o1;
}

// ======================= host launch =============================================
extern "C" void kernel_launch(void* const* d_in, const int* in_sizes, int n_in,
                              void* d_out, int out_size)
{
    const float* feats = (const float*)d_in[0];
    const float* Wk    = (const float*)d_in[1];
    const float* bk    = (const float*)d_in[2];
    const float* Wq    = (const float*)d_in[3];
    const float* bq    = (const float*)d_in[4];
    const float* Wv    = (const float*)d_in[5];
    const float* bv    = (const float*)d_in[6];
    const float* Wa    = (const float*)d_in[7];
    const float* ba    = (const float*)d_in[8];
    const float* ln_w  = (const float*)d_in[9];
    const float* ln_b  = (const float*)d_in[10];
    const float* skip  = (const float*)d_in[11];
    const float* mu    = (const float*)d_in[12];
    const float* w_att = (const float*)d_in[13];
    const float* w_msg = (const float*)d_in[14];
    const int*   src   = (const int*)d_in[15];
    const int*   dst   = (const int*)d_in[16];
    float* out = (float*)d_out;

    static bool attr_done = false;
    if (!attr_done) {
        cudaFuncSetAttribute(hmma_gemm_kernel,
                             cudaFuncAttributeMaxDynamicSharedMemorySize, GEMM_SMEM);
        attr_done = true;
    }

    float *pbcat, *pQKV, *ph, *ptrans;
    __nv_bfloat16 *pWcH, *pWcL, *pWaH, *pWaL;
    cudaGetSymbolAddress((void**)&pbcat, g_bcat);
    cudaGetSymbolAddress((void**)&pQKV, g_QKV);
    cudaGetSymbolAddress((void**)&ph, g_h);
    cudaGetSymbolAddress((void**)&ptrans, g_trans);
    cudaGetSymbolAddress((void**)&pWcH, g_WcatT_hi);
    cudaGetSymbolAddress((void**)&pWcL, g_WcatT_lo);
    cudaGetSymbolAddress((void**)&pWaH, g_WaT_hi);
    cudaGetSymbolAddress((void**)&pWaL, g_WaT_lo);

    // 1. weight prep
    {
        dim3 grid(1024, 2);
        prep_kernel<<<grid, 256>>>(Wk, bk, Wq, bq, Wv, bv, Wa, w_att, w_msg);
    }

    // 2. CSR build
    zerodeg_kernel<<<(2 * NNODE + 255) / 256, 256>>>();
    {
        dim3 grid((EE + 255) / 256, 2);
        hist_kernel<<<grid, 256>>>(dst);
    }
    scan_kernel<<<2, 1024>>>();
    {
        dim3 grid((EE + 255) / 256, 2);
        scatter_kernel<<<grid, 256>>>(src, dst);
    }

    // 3. QKV projection (HMMA, fp32 A = feats directly)
    {
        dim3 grid((NNODE + BM - 1) / BM, QKVW / BN, 2);
        hmma_gemm_kernel<<<grid, 256, GEMM_SMEM>>>(
            feats, (long)NNODE * DDIM,
            pWcH, pWcL, (long)QKVW * DDIM,
            pbcat, (long)QKVW,
            pQKV, (long)NNODE * QKVW,
            NNODE, QKVW);
    }

    // 4. aggregation (scores + softmax + weighted sum, fused; fp32 output)
    {
        dim3 grid((NNODE + 7) / 8, 2);
        agg_kernel<<<grid, 256>>>(mu);
    }

    // 5. output projection (HMMA, fp32 A = g_h)
    {
        dim3 grid((NNODE + BM - 1) / BM, DDIM / BN, 2);
        hmma_gemm_kernel<<<grid, 256, GEMM_SMEM>>>(
            ph, (long)NNODE * DDIM,
            pWaH, pWaL, (long)DDIM * DDIM,
            ba, (long)DDIM,
            ptrans, (long)NNODE * DDIM,
            NNODE, DDIM);
    }

    // 6. skip-mix + LayerNorm -> d_out
    ln_kernel<<<(2 * NNODE) / 8, 256>>>(feats, skip, ln_w, ln_b, out);
}

// round 11
// speedup vs baseline: 1.1809x; 1.0849x over previous
#include <cuda_runtime.h>
#include <cuda_bf16.h>
#include <math.h>
#include <stdint.h>

#define NNODE 50000
#define DDIM  256
#define HH    8
#define EE    500000
#define QKVW  768
#define ATT_SCALE 0.17677669529663687f  // 1/sqrt(32)

#define SCB   512                       // scan elements per block
#define NSCB  ((NNODE + SCB - 1) / SCB) // 98

// ======================= device scratch ==========================================
__device__ float g_bcat[2][QKVW];
__device__ __nv_bfloat16 g_WcatT_hi[2][(size_t)QKVW * DDIM];  // [n][k], n = Q|K'|V'
__device__ __nv_bfloat16 g_WcatT_lo[2][(size_t)QKVW * DDIM];
__device__ __nv_bfloat16 g_WaT_hi[2][(size_t)DDIM * DDIM];
__device__ __nv_bfloat16 g_WaT_lo[2][(size_t)DDIM * DDIM];
__device__ float g_QKV[2][(size_t)NNODE * QKVW];  // fp32: Q(256)|K'(256)|V'(256)
__device__ float g_h[2][(size_t)NNODE * DDIM];    // fp32 aggregated messages
__device__ float g_trans[2][(size_t)NNODE * DDIM];
// CSR-by-destination scratch
__device__ int g_deg[2][NNODE];
__device__ int g_rows[2][NNODE + 1];
__device__ int g_cursor[2][NNODE];
__device__ int g_esrc[2][EE];
__device__ int g_bsum[2][NSCB];
__device__ int g_boff[2][NSCB];

// ======================= PTX helpers (base-target safe) ==========================
__device__ __forceinline__ uint32_t smem_u32(const void* p) {
    uint32_t a;
    asm("{ .reg .u64 t; cvta.to.shared.u64 t, %1; cvt.u32.u64 %0, t; }" : "=r"(a) : "l"(p));
    return a;
}
__device__ __forceinline__ void ldm_x4(uint32_t* r, uint32_t addr) {
    asm volatile("ldmatrix.sync.aligned.m8n8.x4.shared.b16 {%0,%1,%2,%3}, [%4];"
                 : "=r"(r[0]), "=r"(r[1]), "=r"(r[2]), "=r"(r[3]) : "r"(addr));
}
__device__ __forceinline__ void ldm_x2(uint32_t* r, uint32_t addr) {
    asm volatile("ldmatrix.sync.aligned.m8n8.x2.shared.b16 {%0,%1}, [%2];"
                 : "=r"(r[0]), "=r"(r[1]) : "r"(addr));
}
__device__ __forceinline__ void mma_bf16(float* c, const uint32_t* a, const uint32_t* b) {
    asm volatile("mma.sync.aligned.m16n8k16.row.col.f32.bf16.bf16.f32 "
                 "{%0,%1,%2,%3}, {%4,%5,%6,%7}, {%8,%9}, {%0,%1,%2,%3};"
                 : "+f"(c[0]), "+f"(c[1]), "+f"(c[2]), "+f"(c[3])
                 : "r"(a[0]), "r"(a[1]), "r"(a[2]), "r"(a[3]), "r"(b[0]), "r"(b[1]));
}

// split 8 fp32 into bf16 hi/lo packed uint4s
__device__ __forceinline__ void split8(const float4& v0, const float4& v1,
                                       uint4& hiq, uint4& loq) {
    float f[8] = {v0.x, v0.y, v0.z, v0.w, v1.x, v1.y, v1.z, v1.w};
    __nv_bfloat162 hh[4], ll[4];
    #pragma unroll
    for (int j = 0; j < 4; ++j) {
        __nv_bfloat16 h0 = __float2bfloat16(f[2 * j]);
        __nv_bfloat16 h1 = __float2bfloat16(f[2 * j + 1]);
        __nv_bfloat16 l0 = __float2bfloat16(f[2 * j]     - __bfloat162float(h0));
        __nv_bfloat16 l1 = __float2bfloat16(f[2 * j + 1] - __bfloat162float(h1));
        hh[j] = __halves2bfloat162(h0, h1);
        ll[j] = __halves2bfloat162(l0, l1);
    }
    hiq = *(const uint4*)hh;
    loq = *(const uint4*)ll;
}

// ======================= 1. prep: fold + transpose + bf16 split ==================
__global__ __launch_bounds__(256) void prep_kernel(
    const float* __restrict__ Wk, const float* __restrict__ bk,
    const float* __restrict__ Wq, const float* __restrict__ bq,
    const float* __restrict__ Wv, const float* __restrict__ bv,
    const float* __restrict__ Wa,
    const float* __restrict__ w_att, const float* __restrict__ w_msg)
{
    const int t = blockIdx.y;
    const int n = blockIdx.x;
    const int k = threadIdx.x;

    float val;
    if (n < 768) {
        if (n < 256) {
            val = Wq[((size_t)t * 256 + k) * 256 + n];
        } else {
            const int j = (n - 256) & 255;
            const int h = j >> 5, jj = j & 31;
            const float* W = (n < 512) ? Wk : Wv;
            const float* wm = ((n < 512) ? w_att : w_msg) + ((size_t)(t * 8 + h)) * 1024 + jj;
            const float* wrow = W + ((size_t)t * 256 + k) * 256 + h * 32;
            float a = 0.f;
            #pragma unroll 8
            for (int i = 0; i < 32; ++i) a += wrow[i] * wm[i * 32];
            val = a;
        }
        __nv_bfloat16 hi = __float2bfloat16(val);
        __nv_bfloat16 lo = __float2bfloat16(val - __bfloat162float(hi));
        g_WcatT_hi[t][(size_t)n * 256 + k] = hi;
        g_WcatT_lo[t][(size_t)n * 256 + k] = lo;
        if (k == 0) {
            float b;
            if (n < 256) b = bq[t * 256 + n];
            else {
                const int j = (n - 256) & 255;
                const int h = j >> 5, jj = j & 31;
                const float* bb = (n < 512) ? bk : bv;
                const float* wm = ((n < 512) ? w_att : w_msg) + ((size_t)(t * 8 + h)) * 1024 + jj;
                float a = 0.f;
                #pragma unroll 8
                for (int i = 0; i < 32; ++i) a += bb[t * 256 + h * 32 + i] * wm[i * 32];
                b = a;
            }
            g_bcat[t][n] = b;
        }
    } else {
        const int nn = n - 768;
        val = Wa[((size_t)t * 256 + k) * 256 + nn];
        __nv_bfloat16 hi = __float2bfloat16(val);
        __nv_bfloat16 lo = __float2bfloat16(val - __bfloat162float(hi));
        g_WaT_hi[t][(size_t)nn * 256 + k] = hi;
        g_WaT_lo[t][(size_t)nn * 256 + k] = lo;
    }
}

// ======================= 2. CSR build ============================================
__global__ void zerodeg_kernel()
{
    int i = blockIdx.x * blockDim.x + threadIdx.x;
    if (i < 2 * NNODE) ((int*)g_deg)[i] = 0;
}

__global__ void hist_kernel(const int* __restrict__ dst)
{
    const int et = blockIdx.y;
    int e = blockIdx.x * blockDim.x + threadIdx.x;
    if (e >= EE) return;
    atomicAdd(&g_deg[et][dst[(long)et * EE + e]], 1);
}

// phase A: per-block exclusive scan of 512 degs; local offsets + block totals
__global__ __launch_bounds__(SCB) void scanA_kernel()
{
    const int et = blockIdx.y;
    const int b = blockIdx.x;
    const int tid = threadIdx.x;
    const int idx = b * SCB + tid;
    const int lane = tid & 31, w = tid >> 5;

    int d = (idx < NNODE) ? g_deg[et][idx] : 0;
    int x = d;
    #pragma unroll
    for (int o = 1; o < 32; o <<= 1) {
        int n = __shfl_up_sync(0xffffffffu, x, o);
        if (lane >= o) x += n;
    }
    __shared__ int ws[SCB / 32];
    if (lane == 31) ws[w] = x;
    __syncthreads();
    if (w == 0) {
        // ALL 32 lanes execute the shuffles (full-mask requirement);
        // only lanes < SCB/32 carry/commit real data.
        int y = (lane < SCB / 32) ? ws[lane] : 0;
        #pragma unroll
        for (int o = 1; o < SCB / 32; o <<= 1) {
            int n = __shfl_up_sync(0xffffffffu, y, o);
            if (lane >= o) y += n;
        }
        if (lane < SCB / 32) ws[lane] = y;
    }
    __syncthreads();
    const int incl = x + (w > 0 ? ws[w - 1] : 0);
    if (idx < NNODE) g_rows[et][idx] = incl - d;   // local exclusive offset
    if (tid == SCB - 1) g_bsum[et][b] = incl;      // block total
}

// phase B: scan the NSCB block totals (one block per etype)
__global__ __launch_bounds__(128) void scanB_kernel()
{
    const int et = blockIdx.x;
    const int t = threadIdx.x;
    const int lane = t & 31, w = t >> 5;
    int v = (t < NSCB) ? g_bsum[et][t] : 0;
    int x = v;
    #pragma unroll
    for (int o = 1; o < 32; o <<= 1) {
        int n = __shfl_up_sync(0xffffffffu, x, o);
        if (lane >= o) x += n;
    }
    __shared__ int ws[4];
    if (lane == 31) ws[w] = x;
    __syncthreads();
    int add = 0;
    #pragma unroll
    for (int i = 0; i < 4; ++i) if (i < w) add += ws[i];
    const int incl = x + add;
    if (t < NSCB) g_boff[et][t] = incl - v;
    if (t == NSCB - 1) g_rows[et][NNODE] = incl;
}

// phase C: add block offsets; emit rows + cursor
__global__ __launch_bounds__(SCB) void scanC_kernel()
{
    const int et = blockIdx.y;
    const int b = blockIdx.x;
    const int idx = b * SCB + threadIdx.x;
    if (idx >= NNODE) return;
    const int r = g_rows[et][idx] + g_boff[et][b];
    g_rows[et][idx] = r;
    g_cursor[et][idx] = r;
}

__global__ void scatter_kernel(const int* __restrict__ src, const int* __restrict__ dst)
{
    const int et = blockIdx.y;
    int e = blockIdx.x * blockDim.x + threadIdx.x;
    if (e >= EE) return;
    int s = src[(long)et * EE + e];
    int d = dst[(long)et * EE + e];
    int pos = atomicAdd(&g_cursor[et][d], 1);
    g_esrc[et][pos] = s;
}

// ======================= 3. warp-per-dst aggregation (2-edge unroll) ==============
__device__ __forceinline__ float dot8(const float4& qa, const float4& qb,
                                      const float4& ka, const float4& kb) {
    return qa.x * ka.x + qa.y * ka.y + qa.z * ka.z + qa.w * ka.w
         + qb.x * kb.x + qb.y * kb.y + qb.z * kb.z + qb.w * kb.w;
}

__global__ __launch_bounds__(256) void agg_kernel(const float* __restrict__ mu)
{
    const int et = blockIdx.y;
    const int dt = 1 - et;
    const int warp = threadIdx.x >> 5;
    const int lane = threadIdx.x & 31;
    const int node = blockIdx.x * 8 + warp;
    if (node >= NNODE) return;

    const int r0 = g_rows[et][node];
    const int r1 = g_rows[et][node + 1];

    const int h = lane >> 2;
    const int base = lane * 8;
    const float muh = mu[et * 8 + h] * ATT_SCALE;

    float acc[8];
    #pragma unroll
    for (int j = 0; j < 8; ++j) acc[j] = 0.f;
    float wsum = 0.f;

    if (r0 < r1) {
        const float* qrow = g_QKV[dt] + (size_t)node * QKVW + base;
        const float4 qa = *(const float4*)qrow;
        const float4 qb = *(const float4*)(qrow + 4);
        const int* __restrict__ ep = g_esrc[et];
        const float* __restrict__ kvbase = g_QKV[et];

        int j = r0;
        for (; j + 1 < r1; j += 2) {
            const int s0 = ep[j];
            const int s1 = ep[j + 1];
            const float* kr0 = kvbase + (size_t)s0 * QKVW + 256 + base;
            const float* kr1 = kvbase + (size_t)s1 * QKVW + 256 + base;
            float4 ka0 = *(const float4*)kr0;
            float4 kb0 = *(const float4*)(kr0 + 4);
            float4 va0 = *(const float4*)(kr0 + 256);
            float4 vb0 = *(const float4*)(kr0 + 260);
            float4 ka1 = *(const float4*)kr1;
            float4 kb1 = *(const float4*)(kr1 + 4);
            float4 va1 = *(const float4*)(kr1 + 256);
            float4 vb1 = *(const float4*)(kr1 + 260);

            float p0 = dot8(qa, qb, ka0, kb0);
            float p1 = dot8(qa, qb, ka1, kb1);
            p0 += __shfl_xor_sync(0xffffffffu, p0, 1);
            p1 += __shfl_xor_sync(0xffffffffu, p1, 1);
            p0 += __shfl_xor_sync(0xffffffffu, p0, 2);
            p1 += __shfl_xor_sync(0xffffffffu, p1, 2);

            float w0 = expf(p0 * muh);
            float w1 = expf(p1 * muh);
            wsum += w0 + w1;
            acc[0] += w0 * va0.x + w1 * va1.x;
            acc[1] += w0 * va0.y + w1 * va1.y;
            acc[2] += w0 * va0.z + w1 * va1.z;
            acc[3] += w0 * va0.w + w1 * va1.w;
            acc[4] += w0 * vb0.x + w1 * vb1.x;
            acc[5] += w0 * vb0.y + w1 * vb1.y;
            acc[6] += w0 * vb0.z + w1 * vb1.z;
            acc[7] += w0 * vb0.w + w1 * vb1.w;
        }
        if (j < r1) {
            const int s0 = ep[j];
            const float* kr0 = kvbase + (size_t)s0 * QKVW + 256 + base;
            float4 ka0 = *(const float4*)kr0;
            float4 kb0 = *(const float4*)(kr0 + 4);
            float4 va0 = *(const float4*)(kr0 + 256);
            float4 vb0 = *(const float4*)(kr0 + 260);
            float p0 = dot8(qa, qb, ka0, kb0);
            p0 += __shfl_xor_sync(0xffffffffu, p0, 1);
            p0 += __shfl_xor_sync(0xffffffffu, p0, 2);
            float w0 = expf(p0 * muh);
            wsum += w0;
            acc[0] += w0 * va0.x;  acc[1] += w0 * va0.y;
            acc[2] += w0 * va0.z;  acc[3] += w0 * va0.w;
            acc[4] += w0 * vb0.x;  acc[5] += w0 * vb0.y;
            acc[6] += w0 * vb0.z;  acc[7] += w0 * vb0.w;
        }
    }

    const float inv = (wsum > 0.f) ? 1.f / wsum : 0.f;
    float* op = g_h[dt] + (size_t)node * DDIM + base;
    float4 o0 = make_float4(acc[0] * inv, acc[1] * inv, acc[2] * inv, acc[3] * inv);
    float4 o1 = make_float4(acc[4] * inv, acc[5] * inv, acc[6] * inv, acc[7] * inv);
    *(float4*)(op)     = o0;
    *(float4*)(op + 4) = o1;
}

// ======================= 4. split-bf16 HMMA GEMM (fp32 A, in-kernel split) =======
#define BM 128
#define BN 128
#define BK 64
#define LDS_STRIDE 72
#define AS_HI 0
#define AS_LO (AS_HI + BM * LDS_STRIDE * 2)
#define BS_HI (AS_LO + BM * LDS_STRIDE * 2)
#define BS_LO (BS_HI + BN * LDS_STRIDE * 2)
#define GEMM_SMEM (BS_LO + BN * LDS_STRIDE * 2)

__global__ __launch_bounds__(256) void hmma_gemm_kernel(
    const float* __restrict__ A, long strideA,
    const __nv_bfloat16* __restrict__ Bhi, const __nv_bfloat16* __restrict__ Blo, long strideB,
    const float* __restrict__ bias, long strideBias,
    float* __restrict__ C, long strideC,
    int M, int Ntot)
{
    extern __shared__ char smem[];
    const uint32_t sbase = smem_u32(smem);

    const int tid = threadIdx.x;
    const int wid = tid >> 5, lane = tid & 31;
    const int t = blockIdx.z;
    const int m0 = blockIdx.x * BM;
    const int n0 = blockIdx.y * BN;
    const int mw = (wid & 1) * 64;
    const int nw = (wid >> 1) * 32;

    A += (size_t)t * strideA;
    Bhi += (size_t)t * strideB;  Blo += (size_t)t * strideB;
    bias += (size_t)t * strideBias;
    C += (size_t)t * strideC;

    float acc[4][4][4];
    #pragma unroll
    for (int i = 0; i < 4; ++i)
        #pragma unroll
        for (int j = 0; j < 4; ++j)
            #pragma unroll
            for (int r = 0; r < 4; ++r) acc[i][j][r] = 0.f;

    for (int kofs = 0; kofs < 256; kofs += BK) {
        __syncthreads();
        #pragma unroll
        for (int i = 0; i < 4; ++i) {
            int idx = tid + i * 256;
            int row = idx >> 3, c = (idx & 7) * 8;
            uint32_t soff = (uint32_t)(row * LDS_STRIDE + c) * 2;
            float4 v0 = make_float4(0.f, 0.f, 0.f, 0.f);
            float4 v1 = make_float4(0.f, 0.f, 0.f, 0.f);
            int gr = m0 + row;
            if (gr < M) {
                const float* ap = A + (size_t)gr * 256 + kofs + c;
                v0 = *(const float4*)ap;
                v1 = *(const float4*)(ap + 4);
            }
            uint4 hiq, loq;
            split8(v0, v1, hiq, loq);
            *(uint4*)(smem + AS_HI + soff) = hiq;
            *(uint4*)(smem + AS_LO + soff) = loq;
        }
        #pragma unroll
        for (int i = 0; i < 4; ++i) {
            int idx = tid + i * 256;
            int row = idx >> 3, c = (idx & 7) * 8;
            uint32_t soff = (uint32_t)(row * LDS_STRIDE + c) * 2;
            size_t s = (size_t)(n0 + row) * 256 + kofs + c;
            *(uint4*)(smem + BS_HI + soff) = *(const uint4*)(Bhi + s);
            *(uint4*)(smem + BS_LO + soff) = *(const uint4*)(Blo + s);
        }
        __syncthreads();

        #pragma unroll
        for (int kk = 0; kk < BK / 16; ++kk) {
            uint32_t a_hi[4][4], a_lo[4][4], b_hi[4][2], b_lo[4][2];
            #pragma unroll
            for (int i = 0; i < 4; ++i) {
                uint32_t off = (uint32_t)((mw + i * 16 + (lane & 15)) * LDS_STRIDE
                                          + kk * 16 + (lane >> 4) * 8) * 2;
                ldm_x4(a_hi[i], sbase + AS_HI + off);
                ldm_x4(a_lo[i], sbase + AS_LO + off);
            }
            #pragma unroll
            for (int j = 0; j < 4; ++j) {
                uint32_t off = (uint32_t)((nw + j * 8 + (lane & 7)) * LDS_STRIDE
                                          + kk * 16 + ((lane >> 3) & 1) * 8) * 2;
                ldm_x2(b_hi[j], sbase + BS_HI + off);
                ldm_x2(b_lo[j], sbase + BS_LO + off);
            }
            #pragma unroll
            for (int i = 0; i < 4; ++i)
                #pragma unroll
                for (int j = 0; j < 4; ++j) {
                    mma_bf16(acc[i][j], a_hi[i], b_hi[j]);
                    mma_bf16(acc[i][j], a_hi[i], b_lo[j]);
                    mma_bf16(acc[i][j], a_lo[i], b_hi[j]);
                }
        }
    }

    #pragma unroll
    for (int i = 0; i < 4; ++i) {
        int r0 = m0 + mw + i * 16 + (lane >> 2);
        int r1 = r0 + 8;
        #pragma unroll
        for (int j = 0; j < 4; ++j) {
            int col = n0 + nw + j * 8 + (lane & 3) * 2;
            float b0 = bias[col], b1 = bias[col + 1];
            if (r0 < M) {
                float2 o = make_float2(acc[i][j][0] + b0, acc[i][j][1] + b1);
                *(float2*)(C + (size_t)r0 * Ntot + col) = o;
            }
            if (r1 < M) {
                float2 o = make_float2(acc[i][j][2] + b0, acc[i][j][3] + b1);
                *(float2*)(C + (size_t)r1 * Ntot + col) = o;
            }
        }
    }
}

// ======================= 5. skip-mix + LayerNorm =================================
__global__ __launch_bounds__(256) void ln_kernel(
    const float* __restrict__ feats, const float* __restrict__ skip,
    const float* __restrict__ ln_w, const float* __restrict__ ln_b,
    float* __restrict__ out)
{
    long row = (long)blockIdx.x * 8 + (threadIdx.x >> 5);
    const int lane = threadIdx.x & 31;
    const int t = (int)(row / NNODE);
    const float alpha = 1.f / (1.f + expf(-skip[t]));
    const float beta = 1.f - alpha;

    const float* tr = (const float*)g_trans + row * DDIM + lane * 8;
    const float* ft = feats + row * DDIM + lane * 8;

    float v[8];
    float4 t0 = *(const float4*)(tr);
    float4 t1 = *(const float4*)(tr + 4);
    float4 f0 = *(const float4*)(ft);
    float4 f1 = *(const float4*)(ft + 4);
    v[0] = alpha * t0.x + beta * f0.x;  v[1] = alpha * t0.y + beta * f0.y;
    v[2] = alpha * t0.z + beta * f0.z;  v[3] = alpha * t0.w + beta * f0.w;
    v[4] = alpha * t1.x + beta * f1.x;  v[5] = alpha * t1.y + beta * f1.y;
    v[6] = alpha * t1.z + beta * f1.z;  v[7] = alpha * t1.w + beta * f1.w;

    float sum = 0.f, sq = 0.f;
    #pragma unroll
    for (int j = 0; j < 8; ++j) { sum += v[j]; sq += v[j] * v[j]; }
    #pragma unroll
    for (int o = 16; o > 0; o >>= 1) {
        sum += __shfl_xor_sync(0xffffffffu, sum, o);
        sq  += __shfl_xor_sync(0xffffffffu, sq, o);
    }
    const float mean = sum * (1.f / 256.f);
    const float var  = sq * (1.f / 256.f) - mean * mean;
    const float rstd = rsqrtf(var + 1e-5f);

    const int cbase = t * 256 + lane * 8;
    float* op = out + row * DDIM + lane * 8;
    float4 o0, o1;
    o0.x = (v[0] - mean) * rstd * ln_w[cbase + 0] + ln_b[cbase + 0];
    o0.y = (v[1] - mean) * rstd * ln_w[cbase + 1] + ln_b[cbase + 1];
    o0.z = (v[2] - mean) * rstd * ln_w[cbase + 2] + ln_b[cbase + 2];
    o0.w = (v[3] - mean) * rstd * ln_w[cbase + 3] + ln_b[cbase + 3];
    o1.x = (v[4] - mean) * rstd * ln_w[cbase + 4] + ln_b[cbase + 4];
    o1.y = (v[5] - mean) * rstd * ln_w[cbase + 5] + ln_b[cbase + 5];
    o1.z = (v[6] - mean) * rstd * ln_w[cbase + 6] + ln_b[cbase + 6];
    o1.w = (v[7] - mean) * rstd * ln_w[cbase + 7] + ln_b[cbase + 7];
    *(float4*)(op)     = o0;
    *(float4*)(op + 4) = o1;
}

// ======================= host launch =============================================
extern "C" void kernel_launch(void* const* d_in, const int* in_sizes, int n_in,
                              void* d_out, int out_size)
{
    const float* feats = (const float*)d_in[0];
    const float* Wk    = (const float*)d_in[1];
    const float* bk    = (const float*)d_in[2];
    const float* Wq    = (const float*)d_in[3];
    const float* bq    = (const float*)d_in[4];
    const float* Wv    = (const float*)d_in[5];
    const float* bv    = (const float*)d_in[6];
    const float* Wa    = (const float*)d_in[7];
    const float* ba    = (const float*)d_in[8];
    const float* ln_w  = (const float*)d_in[9];
    const float* ln_b  = (const float*)d_in[10];
    const float* skip  = (const float*)d_in[11];
    const float* mu    = (const float*)d_in[12];
    const float* w_att = (const float*)d_in[13];
    const float* w_msg = (const float*)d_in[14];
    const int*   src   = (const int*)d_in[15];
    const int*   dst   = (const int*)d_in[16];
    float* out = (float*)d_out;

    static bool attr_done = false;
    if (!attr_done) {
        cudaFuncSetAttribute(hmma_gemm_kernel,
                             cudaFuncAttributeMaxDynamicSharedMemorySize, GEMM_SMEM);
        attr_done = true;
    }

    float *pbcat, *pQKV, *ph, *ptrans;
    __nv_bfloat16 *pWcH, *pWcL, *pWaH, *pWaL;
    cudaGetSymbolAddress((void**)&pbcat, g_bcat);
    cudaGetSymbolAddress((void**)&pQKV, g_QKV);
    cudaGetSymbolAddress((void**)&ph, g_h);
    cudaGetSymbolAddress((void**)&ptrans, g_trans);
    cudaGetSymbolAddress((void**)&pWcH, g_WcatT_hi);
    cudaGetSymbolAddress((void**)&pWcL, g_WcatT_lo);
    cudaGetSymbolAddress((void**)&pWaH, g_WaT_hi);
    cudaGetSymbolAddress((void**)&pWaL, g_WaT_lo);

    // 1. weight prep
    {
        dim3 grid(1024, 2);
        prep_kernel<<<grid, 256>>>(Wk, bk, Wq, bq, Wv, bv, Wa, w_att, w_msg);
    }

    // 2. CSR build (multi-block scan)
    zerodeg_kernel<<<(2 * NNODE + 255) / 256, 256>>>();
    {
        dim3 grid((EE + 255) / 256, 2);
        hist_kernel<<<grid, 256>>>(dst);
    }
    {
        dim3 grid(NSCB, 2);
        scanA_kernel<<<grid, SCB>>>();
    }
    scanB_kernel<<<2, 128>>>();
    {
        dim3 grid(NSCB, 2);
        scanC_kernel<<<grid, SCB>>>();
    }
    {
        dim3 grid((EE + 255) / 256, 2);
        scatter_kernel<<<grid, 256>>>(src, dst);
    }

    // 3. QKV projection (HMMA, fp32 A = feats directly)
    {
        dim3 grid((NNODE + BM - 1) / BM, QKVW / BN, 2);
        hmma_gemm_kernel<<<grid, 256, GEMM_SMEM>>>(
            feats, (long)NNODE * DDIM,
            pWcH, pWcL, (long)QKVW * DDIM,
            pbcat, (long)QKVW,
            pQKV, (long)NNODE * QKVW,
            NNODE, QKVW);
    }

    // 4. aggregation
    {
        dim3 grid((NNODE + 7) / 8, 2);
        agg_kernel<<<grid, 256>>>(mu);
    }

    // 5. output projection (HMMA, fp32 A = g_h)
    {
        dim3 grid((NNODE + BM - 1) / BM, DDIM / BN, 2);
        hmma_gemm_kernel<<<grid, 256, GEMM_SMEM>>>(
            ph, (long)NNODE * DDIM,
            pWaH, pWaL, (long)DDIM * DDIM,
            ba, (long)DDIM,
            ptrans, (long)NNODE * DDIM,
            NNODE, DDIM);
    }

    // 6. skip-mix + LayerNorm -> d_out
    ln_kernel<<<(2 * NNODE) / 8, 256>>>(feats, skip, ln_w, ln_b, out);
}